// round 2
// baseline (speedup 1.0000x reference)
#include <cuda_runtime.h>
#include <cuda_bf16.h>
#include <cstdint>

#define N_NODES 100000
#define N_EDGES 1000000
#define D 64

// Scratch: agg buffer (holds h = (1+eps)x + sum_neighbors before MLP)
__device__ float g_agg[N_NODES * D];

// ---------------------------------------------------------------------------
// Kernel 1: agg[i] = (1+eps) * x[i]   (fused init, no separate zeroing)
// ---------------------------------------------------------------------------
__global__ void init_agg_kernel(const float4* __restrict__ x,
                                const float* __restrict__ eps,
                                float4* __restrict__ agg) {
    int i = blockIdx.x * blockDim.x + threadIdx.x;
    const int n = N_NODES * (D / 4);
    if (i < n) {
        float s = 1.0f + *eps;
        float4 v = x[i];
        v.x *= s; v.y *= s; v.z *= s; v.w *= s;
        agg[i] = v;
    }
}

// ---------------------------------------------------------------------------
// Kernel 2: scatter-add. 16 threads per edge, one float4 each.
// edge_index is int32 (JAX downcasts int64 without x64 enabled).
// Uses red.global.add.v4.f32 (sm_90+) -> 4x fewer atomic ops than scalar.
// ---------------------------------------------------------------------------
__global__ void scatter_kernel(const float4* __restrict__ x,
                               const int* __restrict__ ei,
                               float* __restrict__ agg) {
    int idx = blockIdx.x * blockDim.x + threadIdx.x;
    if (idx >= N_EDGES * 16) return;
    int e = idx >> 4;
    int j = idx & 15;
    int src = ei[e];
    int dst = ei[N_EDGES + e];
    if ((unsigned)src >= N_NODES || (unsigned)dst >= N_NODES) return;  // safety
    float4 v = x[src * 16 + j];
    float* p = agg + ((long long)dst * D + j * 4);
    asm volatile("red.global.add.v4.f32 [%0], {%1, %2, %3, %4};"
                 :: "l"(p), "f"(v.x), "f"(v.y), "f"(v.z), "f"(v.w)
                 : "memory");
}

// ---------------------------------------------------------------------------
// Kernel 3: fused 2-layer MLP with LeakyReLU.
//   h = leaky(h @ W1 + b1); h = leaky(h @ W2 + b2)
// 64 rows per block, 256 threads: each thread = 2 rows x 8 cols.
// Layer 2 computed in-place over the layer-1 tile (smem reuse).
// ---------------------------------------------------------------------------
#define MLP_ROWS 64
#define XS_STRIDE 66   // pad: avoids bank conflicts on per-row broadcast reads

__device__ __forceinline__ float leaky(float v) {
    return fmaxf(v, 0.01f * v);
}

__global__ __launch_bounds__(256, 2)
void mlp_kernel(const float* __restrict__ agg,
                const float* __restrict__ W1, const float* __restrict__ b1,
                const float* __restrict__ W2, const float* __restrict__ b2,
                float* __restrict__ out) {
    __shared__ float Xs[MLP_ROWS][XS_STRIDE];   // 16.9 KB
    __shared__ float Ws[D][D];                  // 16 KB (W1 then W2)
    __shared__ float bs[D];

    const int tid = threadIdx.x;
    const int cg  = tid & 7;        // col group: 8 cols each
    const int rg  = tid >> 3;       // row group: 2 rows each (32 groups)
    const int row_base = blockIdx.x * MLP_ROWS;

    // --- load X tile (coalesced float2; stride-66 rows are float2-aligned) ---
    {
        const float2* src = (const float2*)(agg + (long long)row_base * D);
        for (int idx = tid; idx < MLP_ROWS * (D / 2); idx += 256) {
            int r = idx >> 5;           // /32
            int p = idx & 31;
            float2 v;
            if (row_base + r < N_NODES) v = src[r * 32 + p];
            else { v.x = 0.f; v.y = 0.f; }
            Xs[r][p * 2]     = v.x;
            Xs[r][p * 2 + 1] = v.y;
        }
    }
    // --- load W1, b1 ---
    {
        const float4* w = (const float4*)W1;
        float4* ws = (float4*)&Ws[0][0];
        for (int idx = tid; idx < D * D / 4; idx += 256) ws[idx] = w[idx];
        if (tid < D) bs[tid] = b1[tid];
    }
    __syncthreads();

    const int r0 = rg * 2;
    const int c0 = cg * 8;

    // ---------------- layer 1 ----------------
    float acc[2][8];
    #pragma unroll
    for (int j = 0; j < 8; j++) { acc[0][j] = bs[c0 + j]; acc[1][j] = bs[c0 + j]; }

    #pragma unroll 8
    for (int k = 0; k < D; k++) {
        float x0 = Xs[r0][k];
        float x1 = Xs[r0 + 1][k];
        float4 wlo = *(const float4*)&Ws[k][c0];
        float4 whi = *(const float4*)&Ws[k][c0 + 4];
        acc[0][0] = fmaf(x0, wlo.x, acc[0][0]); acc[1][0] = fmaf(x1, wlo.x, acc[1][0]);
        acc[0][1] = fmaf(x0, wlo.y, acc[0][1]); acc[1][1] = fmaf(x1, wlo.y, acc[1][1]);
        acc[0][2] = fmaf(x0, wlo.z, acc[0][2]); acc[1][2] = fmaf(x1, wlo.z, acc[1][2]);
        acc[0][3] = fmaf(x0, wlo.w, acc[0][3]); acc[1][3] = fmaf(x1, wlo.w, acc[1][3]);
        acc[0][4] = fmaf(x0, whi.x, acc[0][4]); acc[1][4] = fmaf(x1, whi.x, acc[1][4]);
        acc[0][5] = fmaf(x0, whi.y, acc[0][5]); acc[1][5] = fmaf(x1, whi.y, acc[1][5]);
        acc[0][6] = fmaf(x0, whi.z, acc[0][6]); acc[1][6] = fmaf(x1, whi.z, acc[1][6]);
        acc[0][7] = fmaf(x0, whi.w, acc[0][7]); acc[1][7] = fmaf(x1, whi.w, acc[1][7]);
    }
    __syncthreads();   // done reading Xs (layer1 inputs)

    // write leaky(h1) back into Xs in place
    #pragma unroll
    for (int i = 0; i < 2; i++)
        #pragma unroll
        for (int j = 0; j < 8; j++)
            Xs[r0 + i][c0 + j] = leaky(acc[i][j]);

    // --- load W2, b2 ---
    {
        const float4* w = (const float4*)W2;
        float4* ws = (float4*)&Ws[0][0];
        for (int idx = tid; idx < D * D / 4; idx += 256) ws[idx] = w[idx];
        if (tid < D) bs[tid] = b2[tid];
    }
    __syncthreads();

    // ---------------- layer 2 ----------------
    #pragma unroll
    for (int j = 0; j < 8; j++) { acc[0][j] = bs[c0 + j]; acc[1][j] = bs[c0 + j]; }

    #pragma unroll 8
    for (int k = 0; k < D; k++) {
        float x0 = Xs[r0][k];
        float x1 = Xs[r0 + 1][k];
        float4 wlo = *(const float4*)&Ws[k][c0];
        float4 whi = *(const float4*)&Ws[k][c0 + 4];
        acc[0][0] = fmaf(x0, wlo.x, acc[0][0]); acc[1][0] = fmaf(x1, wlo.x, acc[1][0]);
        acc[0][1] = fmaf(x0, wlo.y, acc[0][1]); acc[1][1] = fmaf(x1, wlo.y, acc[1][1]);
        acc[0][2] = fmaf(x0, wlo.z, acc[0][2]); acc[1][2] = fmaf(x1, wlo.z, acc[1][2]);
        acc[0][3] = fmaf(x0, wlo.w, acc[0][3]); acc[1][3] = fmaf(x1, wlo.w, acc[1][3]);
        acc[0][4] = fmaf(x0, whi.x, acc[0][4]); acc[1][4] = fmaf(x1, whi.x, acc[1][4]);
        acc[0][5] = fmaf(x0, whi.y, acc[0][5]); acc[1][5] = fmaf(x1, whi.y, acc[1][5]);
        acc[0][6] = fmaf(x0, whi.z, acc[0][6]); acc[1][6] = fmaf(x1, whi.z, acc[1][6]);
        acc[0][7] = fmaf(x0, whi.w, acc[0][7]); acc[1][7] = fmaf(x1, whi.w, acc[1][7]);
    }

    // --- store output ---
    #pragma unroll
    for (int i = 0; i < 2; i++) {
        int row = row_base + r0 + i;
        if (row < N_NODES) {
            float4 vlo, vhi;
            vlo.x = leaky(acc[i][0]); vlo.y = leaky(acc[i][1]);
            vlo.z = leaky(acc[i][2]); vlo.w = leaky(acc[i][3]);
            vhi.x = leaky(acc[i][4]); vhi.y = leaky(acc[i][5]);
            vhi.z = leaky(acc[i][6]); vhi.w = leaky(acc[i][7]);
            *(float4*)(out + (long long)row * D + c0)     = vlo;
            *(float4*)(out + (long long)row * D + c0 + 4) = vhi;
        }
    }
}

// ---------------------------------------------------------------------------
// launch
// ---------------------------------------------------------------------------
extern "C" void kernel_launch(void* const* d_in, const int* in_sizes, int n_in,
                              void* d_out, int out_size) {
    const float* x   = (const float*)d_in[0];
    const int*   ei  = (const int*)d_in[1];      // int32: JAX downcasts int64
    const float* eps = (const float*)d_in[2];
    const float* W1  = (const float*)d_in[3];
    const float* b1  = (const float*)d_in[4];
    const float* W2  = (const float*)d_in[5];
    const float* b2  = (const float*)d_in[6];
    float* out = (float*)d_out;

    float* agg;
    cudaGetSymbolAddress((void**)&agg, g_agg);

    // 1) agg = (1+eps) * x
    {
        int n = N_NODES * (D / 4);
        init_agg_kernel<<<(n + 255) / 256, 256>>>((const float4*)x, eps,
                                                  (float4*)agg);
    }
    // 2) agg[dst] += x[src]  (vector reductions)
    {
        int total = N_EDGES * 16;
        int blocks = (total + 255) / 256;
        scatter_kernel<<<blocks, 256>>>((const float4*)x, ei, agg);
    }
    // 3) fused MLP
    {
        int blocks = (N_NODES + MLP_ROWS - 1) / MLP_ROWS;
        mlp_kernel<<<blocks, 256>>>(agg, W1, b1, W2, b2, out);
    }
}